// round 6
// baseline (speedup 1.0000x reference)
#include <cuda_runtime.h>
#include <math.h>

#define N_NODESC 20000
#define N_EDGESC 640000
#define FEATC    128
#define N_RBFC   20
#define CUTOFFC  5.0f
#define PIF      3.14159265358979323846f

typedef unsigned long long u64;

// ---------------- f32x2 packed helpers ----------------
__device__ __forceinline__ u64 pack2(float lo, float hi) {
    u64 r; asm("mov.b64 %0, {%1,%2};" : "=l"(r) : "f"(lo), "f"(hi)); return r;
}
__device__ __forceinline__ void unpack2(u64 p, float& lo, float& hi) {
    asm("mov.b64 {%0,%1}, %2;" : "=f"(lo), "=f"(hi) : "l"(p));
}
__device__ __forceinline__ u64 fma2(u64 a, u64 b, u64 c) {
    u64 d; asm("fma.rn.f32x2 %0, %1, %2, %3;" : "=l"(d) : "l"(a), "l"(b), "l"(c)); return d;
}
__device__ __forceinline__ u64 mul2(u64 a, u64 b) {
    u64 d; asm("mul.rn.f32x2 %0, %1, %2;" : "=l"(d) : "l"(a), "l"(b)); return d;
}
__device__ __forceinline__ u64 add2(u64 a, u64 b) {
    u64 d; asm("add.rn.f32x2 %0, %1, %2;" : "=l"(d) : "l"(a), "l"(b)); return d;
}

// ---------------- scratch (__device__ globals; no allocation) ----------------
__device__ __align__(16) float g_phi[N_NODESC * 3 * FEATC];   // phi_node, [N,384]
__device__ __align__(16) int   g_count[N_NODESC];
__device__ __align__(16) int   g_cursor[N_NODESC];
__device__ __align__(16) int   g_rowptr[N_NODESC + 1];
__device__ __align__(16) int   g_eid[N_EDGESC];
__device__ __align__(16) int   g_src[N_EDGESC];
__device__ __align__(16) int   g_dst[N_EDGESC];
__device__ int g_flag;   // 0 -> nbrs is int64, nonzero -> int32

// ---------------- zero counters ----------------
__global__ void zero_kernel() {
    int i = blockIdx.x * blockDim.x + threadIdx.x;
    if (i < N_NODESC) { g_count[i] = 0; g_cursor[i] = 0; }
    if (i == 0) g_flag = 0;
}

// ---------------- dtype probe ----------------
__global__ void detect_kernel(const int* __restrict__ nbrs32) {
    int t = threadIdx.x;
    int v = nbrs32[2 * t + 1];
    __shared__ int red[1024];
    red[t] = v;
    __syncthreads();
    for (int off = 512; off > 0; off >>= 1) {
        if (t < off) red[t] |= red[t + off];
        __syncthreads();
    }
    if (t == 0) g_flag = red[0];
}

// ---------------- normalize indices to int32 SoA + degree count ----------------
__global__ void extract_kernel(const void* __restrict__ nbrs) {
    int e = blockIdx.x * blockDim.x + threadIdx.x;
    if (e >= N_EDGESC) return;
    int si, di;
    if (g_flag != 0) {
        const int* p = (const int*)nbrs;
        si = p[2 * e]; di = p[2 * e + 1];
    } else {
        const long long* p = (const long long*)nbrs;
        si = (int)p[2 * (long long)e]; di = (int)p[2 * (long long)e + 1];
    }
    g_src[e] = si;
    g_dst[e] = di;
    atomicAdd(&g_count[si], 1);
}

// ---------------- fused node MLP: phi = silu(s@W1+b1)@W2 + b2 ----------------
// 128 threads, 32 nodes/block. Thread tile: 4 nodes x 8 cols, f32x2 packed FMA.
// NOTE: ulonglong2 = 16B = 4 floats. W1 row = 128 fl = 32 u2; W2 row = 384 fl = 96 u2.
#define SPAD 132
__global__ __launch_bounds__(128) void phi_kernel(
    const float* __restrict__ s,
    const float* __restrict__ W1, const float* __restrict__ b1,
    const float* __restrict__ W2, const float* __restrict__ b2)
{
    __shared__ __align__(16) float s_sm[32][SPAD];
    __shared__ __align__(16) float h_sm[32][SPAD];
    int tid = threadIdx.x;
    int node0 = blockIdx.x * 32;

    {   // load 32 rows of s (128 floats each) into padded smem
        const float4* s4 = (const float4*)(s + (size_t)node0 * FEATC);
        for (int idx = tid; idx < 32 * 32; idx += 128) {
            int row = idx >> 5, c = idx & 31;
            *(float4*)&s_sm[row][c * 4] = s4[row * 32 + c];
        }
    }
    __syncthreads();

    int cx = tid & 15;    // col octet: cols 8cx..8cx+7
    int ny = tid >> 4;    // node quad: rows 4ny..4ny+3

    // ---- stage 1: h = silu(s@W1 + b1) ----
    {
        u64 acc[4][4];
        #pragma unroll
        for (int i = 0; i < 4; i++)
            #pragma unroll
            for (int p = 0; p < 4; p++) acc[i][p] = 0ull;
        const ulonglong2* W1q = (const ulonglong2*)W1;  // 32 u2 per row
        #pragma unroll 4
        for (int k = 0; k < FEATC; k += 2) {
            ulonglong2 wA0 = W1q[(size_t)k * 32 + 2 * cx];
            ulonglong2 wA1 = W1q[(size_t)k * 32 + 2 * cx + 1];
            ulonglong2 wB0 = W1q[(size_t)(k + 1) * 32 + 2 * cx];
            ulonglong2 wB1 = W1q[(size_t)(k + 1) * 32 + 2 * cx + 1];
            #pragma unroll
            for (int i = 0; i < 4; i++) {
                float2 a2 = *(const float2*)&s_sm[ny * 4 + i][k];
                u64 aA = pack2(a2.x, a2.x);
                u64 aB = pack2(a2.y, a2.y);
                acc[i][0] = fma2(aA, wA0.x, acc[i][0]);
                acc[i][1] = fma2(aA, wA0.y, acc[i][1]);
                acc[i][2] = fma2(aA, wA1.x, acc[i][2]);
                acc[i][3] = fma2(aA, wA1.y, acc[i][3]);
                acc[i][0] = fma2(aB, wB0.x, acc[i][0]);
                acc[i][1] = fma2(aB, wB0.y, acc[i][1]);
                acc[i][2] = fma2(aB, wB1.x, acc[i][2]);
                acc[i][3] = fma2(aB, wB1.y, acc[i][3]);
            }
        }
        float2 bv[4];
        #pragma unroll
        for (int p = 0; p < 4; p++) bv[p] = *(const float2*)&b1[cx * 8 + p * 2];
        #pragma unroll
        for (int i = 0; i < 4; i++) {
            float h[8];
            #pragma unroll
            for (int p = 0; p < 4; p++) {
                float lo, hi; unpack2(acc[i][p], lo, hi);
                float x0 = lo + bv[p].x, x1 = hi + bv[p].y;
                h[2 * p]     = x0 / (1.0f + expf(-x0));
                h[2 * p + 1] = x1 / (1.0f + expf(-x1));
            }
            *(float4*)&h_sm[ny * 4 + i][cx * 8]     = make_float4(h[0], h[1], h[2], h[3]);
            *(float4*)&h_sm[ny * 4 + i][cx * 8 + 4] = make_float4(h[4], h[5], h[6], h[7]);
        }
    }
    __syncthreads();

    // ---- stage 2: phi = h@W2 + b2 (3 col-groups of 128) ----
    // W2 row = 96 u2; col group g at float g*128 = u2 g*32.
    const ulonglong2* W2q = (const ulonglong2*)W2;
    for (int g = 0; g < 3; g++) {
        u64 acc[4][4];
        #pragma unroll
        for (int i = 0; i < 4; i++)
            #pragma unroll
            for (int p = 0; p < 4; p++) acc[i][p] = 0ull;
        #pragma unroll 4
        for (int k = 0; k < FEATC; k += 2) {
            ulonglong2 wA0 = W2q[(size_t)k * 96 + g * 32 + 2 * cx];
            ulonglong2 wA1 = W2q[(size_t)k * 96 + g * 32 + 2 * cx + 1];
            ulonglong2 wB0 = W2q[(size_t)(k + 1) * 96 + g * 32 + 2 * cx];
            ulonglong2 wB1 = W2q[(size_t)(k + 1) * 96 + g * 32 + 2 * cx + 1];
            #pragma unroll
            for (int i = 0; i < 4; i++) {
                float2 a2 = *(const float2*)&h_sm[ny * 4 + i][k];
                u64 aA = pack2(a2.x, a2.x);
                u64 aB = pack2(a2.y, a2.y);
                acc[i][0] = fma2(aA, wA0.x, acc[i][0]);
                acc[i][1] = fma2(aA, wA0.y, acc[i][1]);
                acc[i][2] = fma2(aA, wA1.x, acc[i][2]);
                acc[i][3] = fma2(aA, wA1.y, acc[i][3]);
                acc[i][0] = fma2(aB, wB0.x, acc[i][0]);
                acc[i][1] = fma2(aB, wB0.y, acc[i][1]);
                acc[i][2] = fma2(aB, wB1.x, acc[i][2]);
                acc[i][3] = fma2(aB, wB1.y, acc[i][3]);
            }
        }
        float2 bv[4];
        #pragma unroll
        for (int p = 0; p < 4; p++) bv[p] = *(const float2*)&b2[g * 128 + cx * 8 + p * 2];
        #pragma unroll
        for (int i = 0; i < 4; i++) {
            float o[8];
            #pragma unroll
            for (int p = 0; p < 4; p++) {
                float lo, hi; unpack2(acc[i][p], lo, hi);
                o[2 * p]     = lo + bv[p].x;
                o[2 * p + 1] = hi + bv[p].y;
            }
            float* dst = &g_phi[(size_t)(node0 + ny * 4 + i) * 384 + g * 128 + cx * 8];
            *(float4*)dst       = make_float4(o[0], o[1], o[2], o[3]);
            *(float4*)(dst + 4) = make_float4(o[4], o[5], o[6], o[7]);
        }
    }
}

// ---------------- CSR scan + scatter ----------------
__global__ void scan_kernel() {
    __shared__ int sm[1024];
    __shared__ int carry_sm;
    int t = threadIdx.x;
    if (t == 0) carry_sm = 0;
    __syncthreads();
    for (int base = 0; base < N_NODESC; base += 1024) {
        int idx = base + t;
        int v = (idx < N_NODESC) ? g_count[idx] : 0;
        int x = v;
        sm[t] = x;
        __syncthreads();
        for (int off = 1; off < 1024; off <<= 1) {
            int y = (t >= off) ? sm[t - off] : 0;
            __syncthreads();
            x += y;
            sm[t] = x;
            __syncthreads();
        }
        int carry = carry_sm;
        if (idx < N_NODESC) g_rowptr[idx] = carry + x - v;
        __syncthreads();
        if (t == 1023) carry_sm = carry + x;
        __syncthreads();
    }
    if (t == 0) g_rowptr[N_NODESC] = carry_sm;
}

__global__ void scatter_kernel() {
    int e = blockIdx.x * blockDim.x + threadIdx.x;
    if (e < N_EDGESC) {
        int i = g_src[e];
        int pos = g_rowptr[i] + atomicAdd(&g_cursor[i], 1);
        g_eid[pos] = e;
    }
}

// ---------------- node-parallel accumulate ----------------
// 64 threads/block, 1 node at a time, 2 adjacent features per thread.
#define STAGE 64
#define GROW  22   // float2 stride per staged edge (176B, 16B-aligned)
__global__ __launch_bounds__(64) void accum_kernel(
    const float* __restrict__ v_j, const float* __restrict__ r_ij,
    const float* __restrict__ Wd, const float* __restrict__ bd,
    float* __restrict__ out_s, float* __restrict__ out_v)
{
    __shared__ __align__(16) float2 sm_g2[STAGE][GROW];  // (g,g) dup pairs, 20 used
    __shared__ __align__(16) float4 sm_geo[STAGE];       // u0,u1,u2,env
    __shared__ int sm_j[STAGE];

    int lt = threadIdx.x;       // 0..63
    int f0 = 2 * lt;            // features f0, f0+1

    // Wd column pairs for (f0, f0+1), packed
    u64 wd0p[N_RBFC], wd1p[N_RBFC], wd2p[N_RBFC];
    #pragma unroll
    for (int k = 0; k < N_RBFC; k++) {
        float2 t0 = *(const float2*)&Wd[k * 384 + f0];
        float2 t1 = *(const float2*)&Wd[k * 384 + 128 + f0];
        float2 t2 = *(const float2*)&Wd[k * 384 + 256 + f0];
        wd0p[k] = pack2(t0.x, t0.y);
        wd1p[k] = pack2(t1.x, t1.y);
        wd2p[k] = pack2(t2.x, t2.y);
    }
    float2 bdt;
    bdt = *(const float2*)&bd[f0];        u64 bd0p = pack2(bdt.x, bdt.y);
    bdt = *(const float2*)&bd[128 + f0];  u64 bd1p = pack2(bdt.x, bdt.y);
    bdt = *(const float2*)&bd[256 + f0];  u64 bd2p = pack2(bdt.x, bdt.y);

    for (int node = blockIdx.x; node < N_NODESC; node += gridDim.x) {
        int start = g_rowptr[node];
        int end   = g_rowptr[node + 1];
        float accs0 = 0.f, accs1 = 0.f;
        float av0a = 0.f, av1a = 0.f, av2a = 0.f;
        float av0b = 0.f, av1b = 0.f, av2b = 0.f;

        for (int base = start; base < end; base += STAGE) {
            int n = end - base; if (n > STAGE) n = STAGE;
            __syncthreads();
            // phase A: stage geometry + duplicated RBF pairs
            if (lt < n) {
                int eid = g_eid[base + lt];
                float r0 = r_ij[3 * (size_t)eid + 0];
                float r1 = r_ij[3 * (size_t)eid + 1];
                float r2 = r_ij[3 * (size_t)eid + 2];
                float d2 = r0 * r0 + r1 * r1 + r2 * r2 + 3e-15f;
                float d  = sqrtf(d2);
                float rinv = 1.0f / d;
                float x = (PIF / CUTOFFC) * d;
                float sx, cxx;
                sincosf(x, &sx, &cxx);
                float env = (d < CUTOFFC) ? 0.5f * (cxx + 1.0f) : 0.0f;
                sm_geo[lt] = make_float4(r0 * rinv, r1 * rinv, r2 * rinv, env);
                float scale = env * rinv;
                float twoc = 2.0f * cxx;
                float sp = 0.0f, sc = sx;   // sin(k*x) Chebyshev recurrence
                #pragma unroll
                for (int k = 0; k < N_RBFC; k++) {
                    float g = sc * scale;
                    sm_g2[lt][k] = make_float2(g, g);
                    float sn = twoc * sc - sp;
                    sp = sc; sc = sn;
                }
                sm_j[lt] = g_dst[eid];
            }
            __syncthreads();
            // phase B: all 64 threads accumulate this batch
            for (int e = 0; e < n; e++) {
                int j = sm_j[e];
                float4 geo = sm_geo[e];
                u64 envp = pack2(geo.w, geo.w);
                u64 A0 = mul2(bd0p, envp), B0 = 0ull;
                u64 A1 = mul2(bd1p, envp), B1 = 0ull;
                u64 A2 = mul2(bd2p, envp), B2 = 0ull;
                const ulonglong2* gq = (const ulonglong2*)&sm_g2[e][0];
                #pragma unroll
                for (int k = 0; k < N_RBFC / 2; k++) {
                    ulonglong2 q = gq[k];
                    A0 = fma2(q.x, wd0p[2 * k], A0);
                    A1 = fma2(q.x, wd1p[2 * k], A1);
                    A2 = fma2(q.x, wd2p[2 * k], A2);
                    B0 = fma2(q.y, wd0p[2 * k + 1], B0);
                    B1 = fma2(q.y, wd1p[2 * k + 1], B1);
                    B2 = fma2(q.y, wd2p[2 * k + 1], B2);
                }
                u64 ws0 = add2(A0, B0);
                u64 ws1 = add2(A1, B1);
                u64 ws2 = add2(A2, B2);
                float w0a, w0b, w1a, w1b, w2a, w2b;
                unpack2(ws0, w0a, w0b);
                unpack2(ws1, w1a, w1b);
                unpack2(ws2, w2a, w2b);

                const float* ph = g_phi + (size_t)j * 384 + f0;
                float2 p0 = *(const float2*)ph;
                float2 p1 = *(const float2*)(ph + 128);
                float2 p2 = *(const float2*)(ph + 256);
                const float* vv = v_j + (size_t)j * 384 + 3 * f0;
                float2 va = *(const float2*)vv;        // vx_a, vy_a
                float2 vb = *(const float2*)(vv + 2);  // vz_a, vx_b
                float2 vc = *(const float2*)(vv + 4);  // vy_b, vz_b

                float i0a = p0.x * w0a, i0b = p0.y * w0b;
                float i2a = p2.x * w2a, i2b = p2.y * w2b;
                accs0 += p1.x * w1a;
                accs1 += p1.y * w1b;
                av0a += i2a * geo.x; av0a += i0a * va.x;
                av1a += i2a * geo.y; av1a += i0a * va.y;
                av2a += i2a * geo.z; av2a += i0a * vb.x;
                av0b += i2b * geo.x; av0b += i0b * vb.y;
                av1b += i2b * geo.y; av1b += i0b * vc.x;
                av2b += i2b * geo.z; av2b += i0b * vc.y;
            }
        }
        *(float2*)&out_s[(size_t)node * FEATC + f0] = make_float2(accs0, accs1);
        float* ov = out_v + (size_t)node * 384 + 3 * f0;
        *(float2*)(ov)     = make_float2(av0a, av1a);
        *(float2*)(ov + 2) = make_float2(av2a, av0b);
        *(float2*)(ov + 4) = make_float2(av1b, av2b);
    }
}

// ---------------- launch ----------------
extern "C" void kernel_launch(void* const* d_in, const int* in_sizes, int n_in,
                              void* d_out, int out_size) {
    (void)in_sizes; (void)n_in; (void)out_size;
    const float* s_j  = (const float*)d_in[0];
    const float* v_j  = (const float*)d_in[1];
    const float* r_ij = (const float*)d_in[2];
    const void*  nbrs = d_in[3];
    const float* W1   = (const float*)d_in[4];
    const float* b1   = (const float*)d_in[5];
    const float* W2   = (const float*)d_in[6];
    const float* b2   = (const float*)d_in[7];
    const float* Wd   = (const float*)d_in[8];
    const float* bd   = (const float*)d_in[9];
    float* out   = (float*)d_out;
    float* out_s = out;                              // [N,128]
    float* out_v = out + (size_t)N_NODESC * FEATC;   // [N,128,3]

    zero_kernel<<<(N_NODESC + 255) / 256, 256>>>();
    detect_kernel<<<1, 1024>>>((const int*)nbrs);
    extract_kernel<<<(N_EDGESC + 255) / 256, 256>>>(nbrs);
    phi_kernel<<<N_NODESC / 32, 128>>>(s_j, W1, b1, W2, b2);
    scan_kernel<<<1, 1024>>>();
    scatter_kernel<<<(N_EDGESC + 255) / 256, 256>>>();
    accum_kernel<<<2500, 64>>>(v_j, r_ij, Wd, bd, out_s, out_v);
}